// round 13
// baseline (speedup 1.0000x reference)
#include <cstdint>
#include <cuda_runtime.h>
#include <cuda_bf16.h>

#define TB 4
#define TT 2048

static __device__ __nv_bfloat16 g_xh[8192 * 1024], g_xl[8192 * 1024];
static __device__ __nv_bfloat16 g_Wah[1024 * 3072], g_Wal[1024 * 3072]; // [K][N]
static __device__ __nv_bfloat16 g_Wph[1024 * 1024], g_Wpl[1024 * 1024]; // [K][N]
static __device__ __nv_bfloat16 g_qh[8192 * 3072], g_ql[8192 * 3072];
static __device__ __nv_bfloat16 g_yh[8192 * 1024], g_yl[8192 * 1024];

__device__ __forceinline__ void split_bf16(float x, __nv_bfloat16& hi, __nv_bfloat16& lo) {
    hi = __float2bfloat16(x);
    lo = __float2bfloat16(x - __bfloat162float(hi));
}

__device__ __forceinline__ unsigned pack_bf16x2(float e0, float e1) {
    __nv_bfloat162 t = __floats2bfloat162_rn(e0, e1);
    unsigned r;
    *(__nv_bfloat162*)&r = t;
    return r;
}

__device__ __forceinline__ void cp16(void* sptr, const void* gptr) {
    unsigned s = (unsigned)__cvta_generic_to_shared(sptr);
    asm volatile("cp.async.cg.shared.global [%0], [%1], 16;\n" :: "r"(s), "l"(gptr));
}
__device__ __forceinline__ void cp_commit() {
    asm volatile("cp.async.commit_group;\n");
}
template <int NN> __device__ __forceinline__ void cp_wait() {
    asm volatile("cp.async.wait_group %0;\n" :: "n"(NN));
}

__device__ __forceinline__ unsigned smem_u32(const void* p) {
    return (unsigned)__cvta_generic_to_shared(p);
}

__device__ __forceinline__ void ldsm4(unsigned& r0, unsigned& r1, unsigned& r2,
                                      unsigned& r3, unsigned addr) {
    asm volatile("ldmatrix.sync.aligned.m8n8.x4.shared.b16 {%0,%1,%2,%3}, [%4];"
                 : "=r"(r0), "=r"(r1), "=r"(r2), "=r"(r3) : "r"(addr));
}
__device__ __forceinline__ void ldsm4t(unsigned& r0, unsigned& r1, unsigned& r2,
                                       unsigned& r3, unsigned addr) {
    asm volatile("ldmatrix.sync.aligned.m8n8.x4.trans.shared.b16 {%0,%1,%2,%3}, [%4];"
                 : "=r"(r0), "=r"(r1), "=r"(r2), "=r"(r3) : "r"(addr));
}

#define MMA_BF16(d, a, b0_, b1_)                                                  \
    asm volatile(                                                                 \
        "mma.sync.aligned.m16n8k16.row.col.f32.bf16.bf16.f32 "                    \
        "{%0,%1,%2,%3}, {%4,%5,%6,%7}, {%8,%9}, {%0,%1,%2,%3};\n"                 \
        : "+f"((d)[0]), "+f"((d)[1]), "+f"((d)[2]), "+f"((d)[3])                  \
        : "r"((a)[0]), "r"((a)[1]), "r"((a)[2]), "r"((a)[3]), "r"(b0_), "r"(b1_))

__global__ __launch_bounds__(256) void split_kernel(
    const float4* __restrict__ src, __nv_bfloat16* __restrict__ hi,
    __nv_bfloat16* __restrict__ lo, int n4)
{
    int i = blockIdx.x * blockDim.x + threadIdx.x;
    if (i >= n4) return;
    float4 v = src[i];
    float f[4] = {v.x, v.y, v.z, v.w};
    __nv_bfloat16 h[4], l[4];
#pragma unroll
    for (int j = 0; j < 4; j++) split_bf16(f[j], h[j], l[j]);
    *(uint2*)(hi + i * 4) = *(uint2*)h;
    *(uint2*)(lo + i * 4) = *(uint2*)l;
}

// ---------------------------------------------------------------------------
// GEMM: C[M,N] = Ahl[M,K] @ Bhl[K,N] + bias   (3-term bf16, raw mma+ldmatrix)
// Tile 128x128, BK=32, 256 thr, warp tile 32x64. cp.async double-buffer.
// (R11 winner, unchanged.)
// ---------------------------------------------------------------------------
__global__ __launch_bounds__(256, 2) void gemm_kernel(
    const __nv_bfloat16* __restrict__ Ah_g, const __nv_bfloat16* __restrict__ Al_g,
    const __nv_bfloat16* __restrict__ Bh_g, const __nv_bfloat16* __restrict__ Bl_g,
    const float* __restrict__ bias,
    float* __restrict__ Cf, __nv_bfloat16* __restrict__ Chi, __nv_bfloat16* __restrict__ Clo,
    int M, int N, int K)
{
    extern __shared__ __align__(16) char sm[];
    __nv_bfloat16* Ah = (__nv_bfloat16*)sm;      // [2][128*40] bf16
    __nv_bfloat16* Al = Ah + 2 * 5120;
    __nv_bfloat16* Bh = Al + 2 * 5120;           // [2][32*136] bf16
    __nv_bfloat16* Bl = Bh + 2 * 4352;

    const int tid = threadIdx.x;
    const int wid = tid >> 5;
    const int lane = tid & 31;
    const int wr = wid >> 1;
    const int wc = wid & 1;
    const int bm = blockIdx.y * 128;
    const int bn = blockIdx.x * 128;

    const unsigned Ah_u = smem_u32(Ah);
    const unsigned Al_u = smem_u32(Al);
    const unsigned Bh_u = smem_u32(Bh);
    const unsigned Bl_u = smem_u32(Bl);

    const unsigned laneA = (unsigned)((lane & 15) * 80 + (lane >> 4) * 16);
    const unsigned laneB = (unsigned)((((lane >> 3) & 1) * 8 + (lane & 7)) * 272 +
                                      (lane >> 4) * 16);

    float acc[2][8][4];
#pragma unroll
    for (int mt = 0; mt < 2; mt++)
#pragma unroll
        for (int nt = 0; nt < 8; nt++)
#pragma unroll
            for (int e = 0; e < 4; e++) acc[mt][nt][e] = 0.0f;

#define GEMM_PREFETCH(KT, ST)                                                        \
    {                                                                                \
        int k0 = (KT) * 32;                                                          \
        _Pragma("unroll")                                                            \
        for (int jj = 0; jj < 2; jj++) {                                             \
            int idx = tid * 2 + jj;                                                  \
            int row = idx >> 2, ch = idx & 3;                                        \
            size_t g = (size_t)(bm + row) * K + k0 + ch * 8;                         \
            cp16(&Ah[(ST) * 5120 + row * 40 + ch * 8], Ah_g + g);                    \
            cp16(&Al[(ST) * 5120 + row * 40 + ch * 8], Al_g + g);                    \
        }                                                                            \
        _Pragma("unroll")                                                            \
        for (int jj = 0; jj < 2; jj++) {                                             \
            int idx = tid * 2 + jj;                                                  \
            int row = idx >> 4, ch = idx & 15;                                       \
            size_t g = (size_t)(k0 + row) * N + bn + ch * 8;                         \
            cp16(&Bh[(ST) * 4352 + row * 136 + ch * 8], Bh_g + g);                   \
            cp16(&Bl[(ST) * 4352 + row * 136 + ch * 8], Bl_g + g);                   \
        }                                                                            \
        cp_commit();                                                                 \
    }

    GEMM_PREFETCH(0, 0);

    const int NK = K >> 5;
    for (int kt = 0; kt < NK; kt++) {
        cp_wait<0>();
        __syncthreads();
        if (kt + 1 < NK) { GEMM_PREFETCH(kt + 1, (kt + 1) & 1); }

        const int st = kt & 1;
        const unsigned a_warp = (unsigned)(st * 10240 + wr * 32 * 80) + laneA;
        const unsigned b_warp = (unsigned)(st * 8704 + wc * 128) + laneB;

#pragma unroll
        for (int ks = 0; ks < 2; ks++) {
            unsigned ahf[2][4], alf[2][4];
            const unsigned a_base = a_warp + (unsigned)(ks * 32);
#pragma unroll
            for (int mt = 0; mt < 2; mt++) {
                ldsm4(ahf[mt][0], ahf[mt][1], ahf[mt][2], ahf[mt][3],
                      Ah_u + a_base + mt * (16 * 80));
                ldsm4(alf[mt][0], alf[mt][1], alf[mt][2], alf[mt][3],
                      Al_u + a_base + mt * (16 * 80));
            }
            const unsigned b_base = b_warp + (unsigned)(ks * 16 * 272);
#pragma unroll
            for (int g = 0; g < 4; g++) {
                unsigned h0, h1, h2, h3, e0, e1, e2, e3;
                ldsm4t(h0, h1, h2, h3, Bh_u + b_base + g * 32);
                ldsm4t(e0, e1, e2, e3, Bl_u + b_base + g * 32);
#pragma unroll
                for (int mt = 0; mt < 2; mt++) {
                    float* c0 = acc[mt][2 * g];
                    float* c1 = acc[mt][2 * g + 1];
                    MMA_BF16(c0, ahf[mt], h0, h1);
                    MMA_BF16(c0, ahf[mt], e0, e1);
                    MMA_BF16(c0, alf[mt], h0, h1);
                    MMA_BF16(c1, ahf[mt], h2, h3);
                    MMA_BF16(c1, ahf[mt], e2, e3);
                    MMA_BF16(c1, alf[mt], h2, h3);
                }
            }
        }
    }

    const int lrow = lane >> 2;
    const int lk2 = (lane & 3) * 2;
#pragma unroll
    for (int mt = 0; mt < 2; mt++) {
        const int row0 = bm + wr * 32 + mt * 16 + lrow;
#pragma unroll
        for (int nt = 0; nt < 8; nt++) {
            const int col = bn + wc * 64 + nt * 8 + lk2;
            const float b0 = bias[col], b1 = bias[col + 1];
            float v00 = acc[mt][nt][0] + b0, v01 = acc[mt][nt][1] + b1;
            float v10 = acc[mt][nt][2] + b0, v11 = acc[mt][nt][3] + b1;
            size_t i0 = (size_t)row0 * N + col;
            size_t i1 = i0 + (size_t)8 * N;
            if (Chi) {
                unsigned h0 = pack_bf16x2(v00, v01);
                __nv_bfloat162 hb0 = *(__nv_bfloat162*)&h0;
                unsigned l0 = pack_bf16x2(v00 - __bfloat162float(hb0.x),
                                          v01 - __bfloat162float(hb0.y));
                unsigned h1 = pack_bf16x2(v10, v11);
                __nv_bfloat162 hb1 = *(__nv_bfloat162*)&h1;
                unsigned l1 = pack_bf16x2(v10 - __bfloat162float(hb1.x),
                                          v11 - __bfloat162float(hb1.y));
                *(unsigned*)(Chi + i0) = h0;
                *(unsigned*)(Clo + i0) = l0;
                *(unsigned*)(Chi + i1) = h1;
                *(unsigned*)(Clo + i1) = l1;
            } else {
                float2 f0; f0.x = v00; f0.y = v01;
                float2 f1; f1.x = v10; f1.y = v11;
                *(float2*)(Cf + i0) = f0;
                *(float2*)(Cf + i1) = f1;
            }
        }
    }
}

// ---------------------------------------------------------------------------
// Flash attention (causal), register-resident, ldmatrix K/V fragments.
// 512 threads / 16 warps, Q-tile 256 rows (16 rows/warp), KV tiles of 64.
// ---------------------------------------------------------------------------
__global__ __launch_bounds__(512, 1) void attn_kernel()
{
    extern __shared__ __align__(16) char sm[];
    __nv_bfloat16* Kh = (__nv_bfloat16*)sm;      // [2][64*72]
    __nv_bfloat16* Kl = Kh + 2 * 4608;
    __nv_bfloat16* Vh = Kl + 2 * 4608;
    __nv_bfloat16* Vl = Vh + 2 * 4608;

    const int tid = threadIdx.x;
    const int wid = tid >> 5;        // 0..15
    const int lane = tid & 31;
    const int qt = (gridDim.x - 1) - blockIdx.x;   // heavy tiles first
    const int qs = qt * 256;
    const int bh = blockIdx.y;
    const int b = bh >> 4, h = bh & 15;
    const int wrow = wid * 16;

    const int lrow = lane >> 2;
    const int lk   = (lane & 3) * 2;

    const unsigned Kh_u = smem_u32(Kh);
    const unsigned Kl_u = smem_u32(Kl);
    const unsigned Vh_u = smem_u32(Vh);
    const unsigned Vl_u = smem_u32(Vl);
    const unsigned laneK = (unsigned)(((lane >> 4) * 8 + (lane & 7)) * 144 +
                                      ((lane >> 3) & 1) * 16);
    const unsigned laneV = (unsigned)((((lane >> 3) & 1) * 8 + (lane & 7)) * 144 +
                                      (lane >> 4) * 16);

// 512 threads, 64 rows x 8 chunks = 512 items -> 1 cp16 per buffer per thread
#define ATTN_LOADKV(J, ST)                                                           \
    {                                                                                \
        size_t base = (size_t)(b * TT + (J) * 64) * 3072 + h * 64;                   \
        int row = tid >> 3, ch = tid & 7;                                            \
        size_t g = base + (size_t)row * 3072 + ch * 8;                               \
        cp16(&Kh[(ST) * 4608 + row * 72 + ch * 8], g_qh + 1024 + g);                 \
        cp16(&Kl[(ST) * 4608 + row * 72 + ch * 8], g_ql + 1024 + g);                 \
        cp16(&Vh[(ST) * 4608 + row * 72 + ch * 8], g_qh + 2048 + g);                 \
        cp16(&Vl[(ST) * 4608 + row * 72 + ch * 8], g_ql + 2048 + g);                 \
        cp_commit();                                                                 \
    }

    ATTN_LOADKV(0, 0);

    unsigned qhf[4][4], qlf[4][4];
    {
        const int r0 = qs + wrow + lrow;
        size_t base0 = (size_t)(b * TT + r0) * 3072 + h * 64;
        size_t base1 = base0 + (size_t)8 * 3072;
#pragma unroll
        for (int kc = 0; kc < 4; kc++) {
            int k0 = kc * 16 + lk;
            qhf[kc][0] = *(const unsigned*)(g_qh + base0 + k0);
            qhf[kc][1] = *(const unsigned*)(g_qh + base1 + k0);
            qhf[kc][2] = *(const unsigned*)(g_qh + base0 + k0 + 8);
            qhf[kc][3] = *(const unsigned*)(g_qh + base1 + k0 + 8);
            qlf[kc][0] = *(const unsigned*)(g_ql + base0 + k0);
            qlf[kc][1] = *(const unsigned*)(g_ql + base1 + k0);
            qlf[kc][2] = *(const unsigned*)(g_ql + base0 + k0 + 8);
            qlf[kc][3] = *(const unsigned*)(g_ql + base1 + k0 + 8);
        }
    }

    float oacc[8][4];
#pragma unroll
    for (int nt = 0; nt < 8; nt++)
#pragma unroll
        for (int e = 0; e < 4; e++) oacc[nt][e] = 0.0f;
    float m0 = -1e30f, m1 = -1e30f, l0 = 0.0f, l1 = 0.0f;

    const int r0g = qs + wrow + lrow;
    const int r1g = r0g + 8;
    const int jmax = 4 * qt + 3;

    for (int j = 0; j <= jmax; j++) {
        cp_wait<0>();
        __syncthreads();
        const int st = j & 1;
        if (j < jmax) { ATTN_LOADKV(j + 1, st ^ 1); }

        if (j * 64 > qs + wrow + 15) continue;  // whole warp masked

        const unsigned khq = Kh_u + st * 9216u + laneK;
        const unsigned klq = Kl_u + st * 9216u + laneK;
        float sacc[8][4];
#pragma unroll
        for (int nt = 0; nt < 8; nt++)
            sacc[nt][0] = sacc[nt][1] = sacc[nt][2] = sacc[nt][3] = 0.0f;
#pragma unroll
        for (int nt2 = 0; nt2 < 4; nt2++) {
            float* s0 = sacc[2 * nt2];
            float* s1 = sacc[2 * nt2 + 1];
#pragma unroll
            for (int kc = 0; kc < 4; kc++) {
                unsigned h0, h1, h2, h3, e0, e1, e2, e3;
                ldsm4(h0, h1, h2, h3, khq + nt2 * 2304u + kc * 32u);
                ldsm4(e0, e1, e2, e3, klq + nt2 * 2304u + kc * 32u);
                MMA_BF16(s0, qhf[kc], h0, h1);
                MMA_BF16(s0, qhf[kc], e0, e1);
                MMA_BF16(s0, qlf[kc], h0, h1);
                MMA_BF16(s1, qhf[kc], h2, h3);
                MMA_BF16(s1, qhf[kc], e2, e3);
                MMA_BF16(s1, qlf[kc], h2, h3);
            }
        }

        const bool needmask = (j * 64 + 63 > qs + wrow);
        float mt0 = -1e30f, mt1 = -1e30f;
#pragma unroll
        for (int nt = 0; nt < 8; nt++) {
            float* s = sacc[nt];
            s[0] *= 0.125f; s[1] *= 0.125f; s[2] *= 0.125f; s[3] *= 0.125f;
            if (needmask) {
                int c0 = j * 64 + nt * 8 + lk;
                if (c0     > r0g) s[0] = -1e30f;
                if (c0 + 1 > r0g) s[1] = -1e30f;
                if (c0     > r1g) s[2] = -1e30f;
                if (c0 + 1 > r1g) s[3] = -1e30f;
            }
            mt0 = fmaxf(mt0, fmaxf(s[0], s[1]));
            mt1 = fmaxf(mt1, fmaxf(s[2], s[3]));
        }
        mt0 = fmaxf(mt0, __shfl_xor_sync(0xFFFFFFFFu, mt0, 1));
        mt0 = fmaxf(mt0, __shfl_xor_sync(0xFFFFFFFFu, mt0, 2));
        mt1 = fmaxf(mt1, __shfl_xor_sync(0xFFFFFFFFu, mt1, 1));
        mt1 = fmaxf(mt1, __shfl_xor_sync(0xFFFFFFFFu, mt1, 2));
        float mn0 = fmaxf(m0, mt0), mn1 = fmaxf(m1, mt1);
        float a0 = __expf(m0 - mn0), a1 = __expf(m1 - mn1);
        m0 = mn0; m1 = mn1;

        float ps0 = 0.0f, ps1 = 0.0f;
        unsigned pah[4][4], pal[4][4];
#pragma unroll
        for (int nt = 0; nt < 8; nt++) {
            float* s = sacc[nt];
            float p0 = __expf(s[0] - mn0), p1 = __expf(s[1] - mn0);
            float p2 = __expf(s[2] - mn1), p3 = __expf(s[3] - mn1);
            ps0 += p0 + p1; ps1 += p2 + p3;
            unsigned h01 = pack_bf16x2(p0, p1);
            unsigned h23 = pack_bf16x2(p2, p3);
            __nv_bfloat162 hb01 = *(__nv_bfloat162*)&h01;
            __nv_bfloat162 hb23 = *(__nv_bfloat162*)&h23;
            unsigned lo01 = pack_bf16x2(p0 - __bfloat162float(hb01.x),
                                        p1 - __bfloat162float(hb01.y));
            unsigned lo23 = pack_bf16x2(p2 - __bfloat162float(hb23.x),
                                        p3 - __bfloat162float(hb23.y));
            int kc = nt >> 1, rlo = (nt & 1) * 2;
            pah[kc][rlo]     = h01;
            pah[kc][rlo + 1] = h23;
            pal[kc][rlo]     = lo01;
            pal[kc][rlo + 1] = lo23;
        }
        ps0 += __shfl_xor_sync(0xFFFFFFFFu, ps0, 1);
        ps0 += __shfl_xor_sync(0xFFFFFFFFu, ps0, 2);
        ps1 += __shfl_xor_sync(0xFFFFFFFFu, ps1, 1);
        ps1 += __shfl_xor_sync(0xFFFFFFFFu, ps1, 2);
        l0 = a0 * l0 + ps0;
        l1 = a1 * l1 + ps1;

#pragma unroll
        for (int nt = 0; nt < 8; nt++) {
            oacc[nt][0] *= a0; oacc[nt][1] *= a0;
            oacc[nt][2] *= a1; oacc[nt][3] *= a1;
        }

        const unsigned vhq = Vh_u + st * 9216u + laneV;
        const unsigned vlq = Vl_u + st * 9216u + laneV;
#pragma unroll
        for (int kc = 0; kc < 4; kc++) {
#pragma unroll
            for (int nt2 = 0; nt2 < 4; nt2++) {
                unsigned h0, h1, h2, h3, e0, e1, e2, e3;
                ldsm4t(h0, h1, h2, h3, vhq + kc * 2304u + nt2 * 32u);
                ldsm4t(e0, e1, e2, e3, vlq + kc * 2304u + nt2 * 32u);
                float* o0 = oacc[2 * nt2];
                float* o1 = oacc[2 * nt2 + 1];
                MMA_BF16(o0, pah[kc], h0, h1);
                MMA_BF16(o0, pah[kc], e0, e1);
                MMA_BF16(o0, pal[kc], h0, h1);
                MMA_BF16(o1, pah[kc], h2, h3);
                MMA_BF16(o1, pah[kc], e2, e3);
                MMA_BF16(o1, pal[kc], h2, h3);
            }
        }
    }

    float i0 = 1.0f / l0, i1 = 1.0f / l1;
    size_t wb0 = (size_t)(b * TT + r0g) * 1024 + h * 64 + lk;
    size_t wb1 = wb0 + (size_t)8 * 1024;
#pragma unroll
    for (int nt = 0; nt < 8; nt++) {
        float v00 = oacc[nt][0] * i0, v01 = oacc[nt][1] * i0;
        float v10 = oacc[nt][2] * i1, v11 = oacc[nt][3] * i1;
        unsigned h0 = pack_bf16x2(v00, v01);
        __nv_bfloat162 hb0 = *(__nv_bfloat162*)&h0;
        unsigned lo0 = pack_bf16x2(v00 - __bfloat162float(hb0.x),
                                   v01 - __bfloat162float(hb0.y));
        unsigned h1 = pack_bf16x2(v10, v11);
        __nv_bfloat162 hb1 = *(__nv_bfloat162*)&h1;
        unsigned lo1 = pack_bf16x2(v10 - __bfloat162float(hb1.x),
                                   v11 - __bfloat162float(hb1.y));
        *(unsigned*)(g_yh + wb0 + nt * 8) = h0;
        *(unsigned*)(g_yl + wb0 + nt * 8) = lo0;
        *(unsigned*)(g_yh + wb1 + nt * 8) = h1;
        *(unsigned*)(g_yl + wb1 + nt * 8) = lo1;
    }
}

extern "C" void kernel_launch(void* const* d_in, const int* in_sizes, int n_in,
                              void* d_out, int out_size)
{
    const float* x  = (const float*)d_in[0];
    const float* Wa = (const float*)d_in[2];
    const float* ba = (const float*)d_in[3];
    const float* Wp = (const float*)d_in[4];
    const float* bp = (const float*)d_in[5];
    float* out = (float*)d_out;

    void *xh, *xl, *Wah, *Wal, *Wph, *Wpl, *qh, *ql, *yh, *yl;
    cudaGetSymbolAddress(&xh, g_xh);   cudaGetSymbolAddress(&xl, g_xl);
    cudaGetSymbolAddress(&Wah, g_Wah); cudaGetSymbolAddress(&Wal, g_Wal);
    cudaGetSymbolAddress(&Wph, g_Wph); cudaGetSymbolAddress(&Wpl, g_Wpl);
    cudaGetSymbolAddress(&qh, g_qh);   cudaGetSymbolAddress(&ql, g_ql);
    cudaGetSymbolAddress(&yh, g_yh);   cudaGetSymbolAddress(&yl, g_yl);

    cudaFuncSetAttribute((const void*)gemm_kernel,
                         cudaFuncAttributeMaxDynamicSharedMemorySize, 75776);
    cudaFuncSetAttribute((const void*)attn_kernel,
                         cudaFuncAttributeMaxDynamicSharedMemorySize, 73728);

    split_kernel<<<8192, 256>>>((const float4*)x,  (__nv_bfloat16*)xh,  (__nv_bfloat16*)xl,  8192 * 1024 / 4);
    split_kernel<<<3072, 256>>>((const float4*)Wa, (__nv_bfloat16*)Wah, (__nv_bfloat16*)Wal, 1024 * 3072 / 4);
    split_kernel<<<1024, 256>>>((const float4*)Wp, (__nv_bfloat16*)Wph, (__nv_bfloat16*)Wpl, 1024 * 1024 / 4);

    gemm_kernel<<<dim3(3072 / 128, 8192 / 128), 256, 75776>>>(
        (const __nv_bfloat16*)xh, (const __nv_bfloat16*)xl,
        (const __nv_bfloat16*)Wah, (const __nv_bfloat16*)Wal,
        ba, nullptr, (__nv_bfloat16*)qh, (__nv_bfloat16*)ql,
        8192, 3072, 1024);

    attn_kernel<<<dim3(TT / 256, 64), 512, 73728>>>();

    gemm_kernel<<<dim3(1024 / 128, 8192 / 128), 256, 75776>>>(
        (const __nv_bfloat16*)yh, (const __nv_bfloat16*)yl,
        (const __nv_bfloat16*)Wph, (const __nv_bfloat16*)Wpl,
        bp, out, nullptr, nullptr,
        8192, 1024, 1024);
}

// round 15
// speedup vs baseline: 1.5501x; 1.5501x over previous
#include <cstdint>
#include <cuda_runtime.h>
#include <cuda_bf16.h>

#define TB 4
#define TT 2048

static __device__ __nv_bfloat16 g_xh[8192 * 1024], g_xl[8192 * 1024];
static __device__ __nv_bfloat16 g_Wah[1024 * 3072], g_Wal[1024 * 3072]; // [K][N]
static __device__ __nv_bfloat16 g_Wph[1024 * 1024], g_Wpl[1024 * 1024]; // [K][N]
static __device__ __nv_bfloat16 g_qh[8192 * 3072], g_ql[8192 * 3072];
static __device__ __nv_bfloat16 g_yh[8192 * 1024], g_yl[8192 * 1024];

__device__ __forceinline__ void split_bf16(float x, __nv_bfloat16& hi, __nv_bfloat16& lo) {
    hi = __float2bfloat16(x);
    lo = __float2bfloat16(x - __bfloat162float(hi));
}

__device__ __forceinline__ unsigned pack_bf16x2(float e0, float e1) {
    __nv_bfloat162 t = __floats2bfloat162_rn(e0, e1);
    unsigned r;
    *(__nv_bfloat162*)&r = t;
    return r;
}

__device__ __forceinline__ void cp16(void* sptr, const void* gptr) {
    unsigned s = (unsigned)__cvta_generic_to_shared(sptr);
    asm volatile("cp.async.cg.shared.global [%0], [%1], 16;\n" :: "r"(s), "l"(gptr));
}
__device__ __forceinline__ void cp_commit() {
    asm volatile("cp.async.commit_group;\n");
}
template <int NN> __device__ __forceinline__ void cp_wait() {
    asm volatile("cp.async.wait_group %0;\n" :: "n"(NN));
}

__device__ __forceinline__ unsigned smem_u32(const void* p) {
    return (unsigned)__cvta_generic_to_shared(p);
}

__device__ __forceinline__ void ldsm4(unsigned& r0, unsigned& r1, unsigned& r2,
                                      unsigned& r3, unsigned addr) {
    asm volatile("ldmatrix.sync.aligned.m8n8.x4.shared.b16 {%0,%1,%2,%3}, [%4];"
                 : "=r"(r0), "=r"(r1), "=r"(r2), "=r"(r3) : "r"(addr));
}
__device__ __forceinline__ void ldsm4t(unsigned& r0, unsigned& r1, unsigned& r2,
                                       unsigned& r3, unsigned addr) {
    asm volatile("ldmatrix.sync.aligned.m8n8.x4.trans.shared.b16 {%0,%1,%2,%3}, [%4];"
                 : "=r"(r0), "=r"(r1), "=r"(r2), "=r"(r3) : "r"(addr));
}

#define MMA_BF16(d, a, b0_, b1_)                                                  \
    asm volatile(                                                                 \
        "mma.sync.aligned.m16n8k16.row.col.f32.bf16.bf16.f32 "                    \
        "{%0,%1,%2,%3}, {%4,%5,%6,%7}, {%8,%9}, {%0,%1,%2,%3};\n"                 \
        : "+f"((d)[0]), "+f"((d)[1]), "+f"((d)[2]), "+f"((d)[3])                  \
        : "r"((a)[0]), "r"((a)[1]), "r"((a)[2]), "r"((a)[3]), "r"(b0_), "r"(b1_))

__global__ __launch_bounds__(256) void split_kernel(
    const float4* __restrict__ src, __nv_bfloat16* __restrict__ hi,
    __nv_bfloat16* __restrict__ lo, int n4)
{
    int i = blockIdx.x * blockDim.x + threadIdx.x;
    if (i >= n4) return;
    float4 v = src[i];
    float f[4] = {v.x, v.y, v.z, v.w};
    __nv_bfloat16 h[4], l[4];
#pragma unroll
    for (int j = 0; j < 4; j++) split_bf16(f[j], h[j], l[j]);
    *(uint2*)(hi + i * 4) = *(uint2*)h;
    *(uint2*)(lo + i * 4) = *(uint2*)l;
}

// ---------------------------------------------------------------------------
// GEMM: C[M,N] = Ahl[M,K] @ Bhl[K,N] + bias   (3-term bf16, raw mma+ldmatrix)
// Tile 128x128, BK=32, 256 thr, warp tile 32x64. cp.async double-buffer,
// wait_group<1> pipeline (issue-before-drain).
// ---------------------------------------------------------------------------
__global__ __launch_bounds__(256, 2) void gemm_kernel(
    const __nv_bfloat16* __restrict__ Ah_g, const __nv_bfloat16* __restrict__ Al_g,
    const __nv_bfloat16* __restrict__ Bh_g, const __nv_bfloat16* __restrict__ Bl_g,
    const float* __restrict__ bias,
    float* __restrict__ Cf, __nv_bfloat16* __restrict__ Chi, __nv_bfloat16* __restrict__ Clo,
    int M, int N, int K)
{
    extern __shared__ __align__(16) char sm[];
    __nv_bfloat16* Ah = (__nv_bfloat16*)sm;      // [2][128*40] bf16
    __nv_bfloat16* Al = Ah + 2 * 5120;
    __nv_bfloat16* Bh = Al + 2 * 5120;           // [2][32*136] bf16
    __nv_bfloat16* Bl = Bh + 2 * 4352;

    const int tid = threadIdx.x;
    const int wid = tid >> 5;
    const int lane = tid & 31;
    const int wr = wid >> 1;
    const int wc = wid & 1;
    const int bm = blockIdx.y * 128;
    const int bn = blockIdx.x * 128;

    const unsigned Ah_u = smem_u32(Ah);
    const unsigned Al_u = smem_u32(Al);
    const unsigned Bh_u = smem_u32(Bh);
    const unsigned Bl_u = smem_u32(Bl);

    const unsigned laneA = (unsigned)((lane & 15) * 80 + (lane >> 4) * 16);
    const unsigned laneB = (unsigned)((((lane >> 3) & 1) * 8 + (lane & 7)) * 272 +
                                      (lane >> 4) * 16);

    float acc[2][8][4];
#pragma unroll
    for (int mt = 0; mt < 2; mt++)
#pragma unroll
        for (int nt = 0; nt < 8; nt++)
#pragma unroll
            for (int e = 0; e < 4; e++) acc[mt][nt][e] = 0.0f;

#define GEMM_PREFETCH(KT, ST)                                                        \
    {                                                                                \
        int k0 = (KT) * 32;                                                          \
        _Pragma("unroll")                                                            \
        for (int jj = 0; jj < 2; jj++) {                                             \
            int idx = tid * 2 + jj;                                                  \
            int row = idx >> 2, ch = idx & 3;                                        \
            size_t g = (size_t)(bm + row) * K + k0 + ch * 8;                         \
            cp16(&Ah[(ST) * 5120 + row * 40 + ch * 8], Ah_g + g);                    \
            cp16(&Al[(ST) * 5120 + row * 40 + ch * 8], Al_g + g);                    \
        }                                                                            \
        _Pragma("unroll")                                                            \
        for (int jj = 0; jj < 2; jj++) {                                             \
            int idx = tid * 2 + jj;                                                  \
            int row = idx >> 4, ch = idx & 15;                                       \
            size_t g = (size_t)(k0 + row) * N + bn + ch * 8;                         \
            cp16(&Bh[(ST) * 4352 + row * 136 + ch * 8], Bh_g + g);                   \
            cp16(&Bl[(ST) * 4352 + row * 136 + ch * 8], Bl_g + g);                   \
        }                                                                            \
        cp_commit();                                                                 \
    }

    GEMM_PREFETCH(0, 0);

    const int NK = K >> 5;
    for (int kt = 0; kt < NK; kt++) {
        __syncthreads();
        if (kt + 1 < NK) {
            GEMM_PREFETCH(kt + 1, (kt + 1) & 1);
            cp_wait<1>();
        } else {
            cp_wait<0>();
        }
        __syncthreads();

        const int st = kt & 1;
        const unsigned a_warp = (unsigned)(st * 10240 + wr * 32 * 80) + laneA;
        const unsigned b_warp = (unsigned)(st * 8704 + wc * 128) + laneB;

#pragma unroll
        for (int ks = 0; ks < 2; ks++) {
            unsigned ahf[2][4], alf[2][4];
            const unsigned a_base = a_warp + (unsigned)(ks * 32);
#pragma unroll
            for (int mt = 0; mt < 2; mt++) {
                ldsm4(ahf[mt][0], ahf[mt][1], ahf[mt][2], ahf[mt][3],
                      Ah_u + a_base + mt * (16 * 80));
                ldsm4(alf[mt][0], alf[mt][1], alf[mt][2], alf[mt][3],
                      Al_u + a_base + mt * (16 * 80));
            }
            const unsigned b_base = b_warp + (unsigned)(ks * 16 * 272);
#pragma unroll
            for (int g = 0; g < 4; g++) {
                unsigned h0, h1, h2, h3, e0, e1, e2, e3;
                ldsm4t(h0, h1, h2, h3, Bh_u + b_base + g * 32);
                ldsm4t(e0, e1, e2, e3, Bl_u + b_base + g * 32);
#pragma unroll
                for (int mt = 0; mt < 2; mt++) {
                    float* c0 = acc[mt][2 * g];
                    float* c1 = acc[mt][2 * g + 1];
                    MMA_BF16(c0, ahf[mt], h0, h1);
                    MMA_BF16(c0, ahf[mt], e0, e1);
                    MMA_BF16(c0, alf[mt], h0, h1);
                    MMA_BF16(c1, ahf[mt], h2, h3);
                    MMA_BF16(c1, ahf[mt], e2, e3);
                    MMA_BF16(c1, alf[mt], h2, h3);
                }
            }
        }
    }

    const int lrow = lane >> 2;
    const int lk2 = (lane & 3) * 2;
#pragma unroll
    for (int mt = 0; mt < 2; mt++) {
        const int row0 = bm + wr * 32 + mt * 16 + lrow;
#pragma unroll
        for (int nt = 0; nt < 8; nt++) {
            const int col = bn + wc * 64 + nt * 8 + lk2;
            const float b0 = bias[col], b1 = bias[col + 1];
            float v00 = acc[mt][nt][0] + b0, v01 = acc[mt][nt][1] + b1;
            float v10 = acc[mt][nt][2] + b0, v11 = acc[mt][nt][3] + b1;
            size_t i0 = (size_t)row0 * N + col;
            size_t i1 = i0 + (size_t)8 * N;
            if (Chi) {
                unsigned h0 = pack_bf16x2(v00, v01);
                __nv_bfloat162 hb0 = *(__nv_bfloat162*)&h0;
                unsigned l0 = pack_bf16x2(v00 - __bfloat162float(hb0.x),
                                          v01 - __bfloat162float(hb0.y));
                unsigned h1 = pack_bf16x2(v10, v11);
                __nv_bfloat162 hb1 = *(__nv_bfloat162*)&h1;
                unsigned l1 = pack_bf16x2(v10 - __bfloat162float(hb1.x),
                                          v11 - __bfloat162float(hb1.y));
                *(unsigned*)(Chi + i0) = h0;
                *(unsigned*)(Clo + i0) = l0;
                *(unsigned*)(Chi + i1) = h1;
                *(unsigned*)(Clo + i1) = l1;
            } else {
                float2 f0; f0.x = v00; f0.y = v01;
                float2 f1; f1.x = v10; f1.y = v11;
                *(float2*)(Cf + i0) = f0;
                *(float2*)(Cf + i1) = f1;
            }
        }
    }
}

// ---------------------------------------------------------------------------
// Flash attention (causal), register-resident, ldmatrix K/V fragments.
// 256 threads / 8 warps, Q-tile 128 rows, KV tiles of 64. (R11 winner.)
// ---------------------------------------------------------------------------
__global__ __launch_bounds__(256, 1) void attn_kernel()
{
    extern __shared__ __align__(16) char sm[];
    __nv_bfloat16* Kh = (__nv_bfloat16*)sm;
    __nv_bfloat16* Kl = Kh + 2 * 4608;
    __nv_bfloat16* Vh = Kl + 2 * 4608;
    __nv_bfloat16* Vl = Vh + 2 * 4608;

    const int tid = threadIdx.x;
    const int wid = tid >> 5;
    const int lane = tid & 31;
    const int qt = (gridDim.x - 1) - blockIdx.x;
    const int qs = qt * 128;
    const int bh = blockIdx.y;
    const int b = bh >> 4, h = bh & 15;
    const int wrow = wid * 16;

    const int lrow = lane >> 2;
    const int lk   = (lane & 3) * 2;

    const unsigned Kh_u = smem_u32(Kh);
    const unsigned Kl_u = smem_u32(Kl);
    const unsigned Vh_u = smem_u32(Vh);
    const unsigned Vl_u = smem_u32(Vl);
    const unsigned laneK = (unsigned)(((lane >> 4) * 8 + (lane & 7)) * 144 +
                                      ((lane >> 3) & 1) * 16);
    const unsigned laneV = (unsigned)((((lane >> 3) & 1) * 8 + (lane & 7)) * 144 +
                                      (lane >> 4) * 16);

#define ATTN_LOADKV(J, ST)                                                           \
    {                                                                                \
        size_t base = (size_t)(b * TT + (J) * 64) * 3072 + h * 64;                   \
        _Pragma("unroll")                                                            \
        for (int jj = 0; jj < 2; jj++) {                                             \
            int idx = tid * 2 + jj;                                                  \
            int row = idx >> 3, ch = idx & 7;                                        \
            size_t g = base + (size_t)row * 3072 + ch * 8;                           \
            cp16(&Kh[(ST) * 4608 + row * 72 + ch * 8], g_qh + 1024 + g);             \
            cp16(&Kl[(ST) * 4608 + row * 72 + ch * 8], g_ql + 1024 + g);             \
            cp16(&Vh[(ST) * 4608 + row * 72 + ch * 8], g_qh + 2048 + g);             \
            cp16(&Vl[(ST) * 4608 + row * 72 + ch * 8], g_ql + 2048 + g);             \
        }                                                                            \
        cp_commit();                                                                 \
    }

    ATTN_LOADKV(0, 0);

    unsigned qhf[4][4], qlf[4][4];
    {
        const int r0 = qs + wrow + lrow;
        size_t base0 = (size_t)(b * TT + r0) * 3072 + h * 64;
        size_t base1 = base0 + (size_t)8 * 3072;
#pragma unroll
        for (int kc = 0; kc < 4; kc++) {
            int k0 = kc * 16 + lk;
            qhf[kc][0] = *(const unsigned*)(g_qh + base0 + k0);
            qhf[kc][1] = *(const unsigned*)(g_qh + base1 + k0);
            qhf[kc][2] = *(const unsigned*)(g_qh + base0 + k0 + 8);
            qhf[kc][3] = *(const unsigned*)(g_qh + base1 + k0 + 8);
            qlf[kc][0] = *(const unsigned*)(g_ql + base0 + k0);
            qlf[kc][1] = *(const unsigned*)(g_ql + base1 + k0);
            qlf[kc][2] = *(const unsigned*)(g_ql + base0 + k0 + 8);
            qlf[kc][3] = *(const unsigned*)(g_ql + base1 + k0 + 8);
        }
    }

    float oacc[8][4];
#pragma unroll
    for (int nt = 0; nt < 8; nt++)
#pragma unroll
        for (int e = 0; e < 4; e++) oacc[nt][e] = 0.0f;
    float m0 = -1e30f, m1 = -1e30f, l0 = 0.0f, l1 = 0.0f;

    const int r0g = qs + wrow + lrow;
    const int r1g = r0g + 8;
    const int jmax = 2 * qt + 1;

    for (int j = 0; j <= jmax; j++) {
        cp_wait<0>();
        __syncthreads();
        const int st = j & 1;
        if (j < jmax) { ATTN_LOADKV(j + 1, st ^ 1); }

        if (j * 64 > qs + wrow + 15) continue;

        const unsigned khq = Kh_u + st * 9216u + laneK;
        const unsigned klq = Kl_u + st * 9216u + laneK;
        float sacc[8][4];
#pragma unroll
        for (int nt = 0; nt < 8; nt++)
            sacc[nt][0] = sacc[nt][1] = sacc[nt][2] = sacc[nt][3] = 0.0f;
#pragma unroll
        for (int nt2 = 0; nt2 < 4; nt2++) {
            float* s0 = sacc[2 * nt2];
            float* s1 = sacc[2 * nt2 + 1];
#pragma unroll
            for (int kc = 0; kc < 4; kc++) {
                unsigned h0, h1, h2, h3, e0, e1, e2, e3;
                ldsm4(h0, h1, h2, h3, khq + nt2 * 2304u + kc * 32u);
                ldsm4(e0, e1, e2, e3, klq + nt2 * 2304u + kc * 32u);
                MMA_BF16(s0, qhf[kc], h0, h1);
                MMA_BF16(s0, qhf[kc], e0, e1);
                MMA_BF16(s0, qlf[kc], h0, h1);
                MMA_BF16(s1, qhf[kc], h2, h3);
                MMA_BF16(s1, qhf[kc], e2, e3);
                MMA_BF16(s1, qlf[kc], h2, h3);
            }
        }

        const bool needmask = (j * 64 + 63 > qs + wrow);
        float mt0 = -1e30f, mt1 = -1e30f;
#pragma unroll
        for (int nt = 0; nt < 8; nt++) {
            float* s = sacc[nt];
            s[0] *= 0.125f; s[1] *= 0.125f; s[2] *= 0.125f; s[3] *= 0.125f;
            if (needmask) {
                int c0 = j * 64 + nt * 8 + lk;
                if (c0     > r0g) s[0] = -1e30f;
                if (c0 + 1 > r0g) s[1] = -1e30f;
                if (c0     > r1g) s[2] = -1e30f;
                if (c0 + 1 > r1g) s[3] = -1e30f;
            }
            mt0 = fmaxf(mt0, fmaxf(s[0], s[1]));
            mt1 = fmaxf(mt1, fmaxf(s[2], s[3]));
        }
        mt0 = fmaxf(mt0, __shfl_xor_sync(0xFFFFFFFFu, mt0, 1));
        mt0 = fmaxf(mt0, __shfl_xor_sync(0xFFFFFFFFu, mt0, 2));
        mt1 = fmaxf(mt1, __shfl_xor_sync(0xFFFFFFFFu, mt1, 1));
        mt1 = fmaxf(mt1, __shfl_xor_sync(0xFFFFFFFFu, mt1, 2));
        float mn0 = fmaxf(m0, mt0), mn1 = fmaxf(m1, mt1);
        float a0 = __expf(m0 - mn0), a1 = __expf(m1 - mn1);
        m0 = mn0; m1 = mn1;

        float ps0 = 0.0f, ps1 = 0.0f;
        unsigned pah[4][4], pal[4][4];
#pragma unroll
        for (int nt = 0; nt < 8; nt++) {
            float* s = sacc[nt];
            float p0 = __expf(s[0] - mn0), p1 = __expf(s[1] - mn0);
            float p2 = __expf(s[2] - mn1), p3 = __expf(s[3] - mn1);
            ps0 += p0 + p1; ps1 += p2 + p3;
            unsigned h01 = pack_bf16x2(p0, p1);
            unsigned h23 = pack_bf16x2(p2, p3);
            __nv_bfloat162 hb01 = *(__nv_bfloat162*)&h01;
            __nv_bfloat162 hb23 = *(__nv_bfloat162*)&h23;
            unsigned lo01 = pack_bf16x2(p0 - __bfloat162float(hb01.x),
                                        p1 - __bfloat162float(hb01.y));
            unsigned lo23 = pack_bf16x2(p2 - __bfloat162float(hb23.x),
                                        p3 - __bfloat162float(hb23.y));
            int kc = nt >> 1, rlo = (nt & 1) * 2;
            pah[kc][rlo]     = h01;
            pah[kc][rlo + 1] = h23;
            pal[kc][rlo]     = lo01;
            pal[kc][rlo + 1] = lo23;
        }
        ps0 += __shfl_xor_sync(0xFFFFFFFFu, ps0, 1);
        ps0 += __shfl_xor_sync(0xFFFFFFFFu, ps0, 2);
        ps1 += __shfl_xor_sync(0xFFFFFFFFu, ps1, 1);
        ps1 += __shfl_xor_sync(0xFFFFFFFFu, ps1, 2);
        l0 = a0 * l0 + ps0;
        l1 = a1 * l1 + ps1;

#pragma unroll
        for (int nt = 0; nt < 8; nt++) {
            oacc[nt][0] *= a0; oacc[nt][1] *= a0;
            oacc[nt][2] *= a1; oacc[nt][3] *= a1;
        }

        const unsigned vhq = Vh_u + st * 9216u + laneV;
        const unsigned vlq = Vl_u + st * 9216u + laneV;
#pragma unroll
        for (int kc = 0; kc < 4; kc++) {
#pragma unroll
            for (int nt2 = 0; nt2 < 4; nt2++) {
                unsigned h0, h1, h2, h3, e0, e1, e2, e3;
                ldsm4t(h0, h1, h2, h3, vhq + kc * 2304u + nt2 * 32u);
                ldsm4t(e0, e1, e2, e3, vlq + kc * 2304u + nt2 * 32u);
                float* o0 = oacc[2 * nt2];
                float* o1 = oacc[2 * nt2 + 1];
                MMA_BF16(o0, pah[kc], h0, h1);
                MMA_BF16(o0, pah[kc], e0, e1);
                MMA_BF16(o0, pal[kc], h0, h1);
                MMA_BF16(o1, pah[kc], h2, h3);
                MMA_BF16(o1, pah[kc], e2, e3);
                MMA_BF16(o1, pal[kc], h2, h3);
            }
        }
    }

    float i0 = 1.0f / l0, i1 = 1.0f / l1;
    size_t wb0 = (size_t)(b * TT + r0g) * 1024 + h * 64 + lk;
    size_t wb1 = wb0 + (size_t)8 * 1024;
#pragma unroll
    for (int nt = 0; nt < 8; nt++) {
        float v00 = oacc[nt][0] * i0, v01 = oacc[nt][1] * i0;
        float v10 = oacc[nt][2] * i1, v11 = oacc[nt][3] * i1;
        unsigned h0 = pack_bf16x2(v00, v01);
        __nv_bfloat162 hb0 = *(__nv_bfloat162*)&h0;
        unsigned lo0 = pack_bf16x2(v00 - __bfloat162float(hb0.x),
                                   v01 - __bfloat162float(hb0.y));
        unsigned h1 = pack_bf16x2(v10, v11);
        __nv_bfloat162 hb1 = *(__nv_bfloat162*)&h1;
        unsigned lo1 = pack_bf16x2(v10 - __bfloat162float(hb1.x),
                                   v11 - __bfloat162float(hb1.y));
        *(unsigned*)(g_yh + wb0 + nt * 8) = h0;
        *(unsigned*)(g_yl + wb0 + nt * 8) = lo0;
        *(unsigned*)(g_yh + wb1 + nt * 8) = h1;
        *(unsigned*)(g_yl + wb1 + nt * 8) = lo1;
    }
}

extern "C" void kernel_launch(void* const* d_in, const int* in_sizes, int n_in,
                              void* d_out, int out_size)
{
    const float* x  = (const float*)d_in[0];
    const float* Wa = (const float*)d_in[2];
    const float* ba = (const float*)d_in[3];
    const float* Wp = (const float*)d_in[4];
    const float* bp = (const float*)d_in[5];
    float* out = (float*)d_out;

    void *xh, *xl, *Wah, *Wal, *Wph, *Wpl, *qh, *ql, *yh, *yl;
    cudaGetSymbolAddress(&xh, g_xh);   cudaGetSymbolAddress(&xl, g_xl);
    cudaGetSymbolAddress(&Wah, g_Wah); cudaGetSymbolAddress(&Wal, g_Wal);
    cudaGetSymbolAddress(&Wph, g_Wph); cudaGetSymbolAddress(&Wpl, g_Wpl);
    cudaGetSymbolAddress(&qh, g_qh);   cudaGetSymbolAddress(&ql, g_ql);
    cudaGetSymbolAddress(&yh, g_yh);   cudaGetSymbolAddress(&yl, g_yl);

    cudaFuncSetAttribute((const void*)gemm_kernel,
                         cudaFuncAttributeMaxDynamicSharedMemorySize, 75776);
    cudaFuncSetAttribute((const void*)attn_kernel,
                         cudaFuncAttributeMaxDynamicSharedMemorySize, 73728);

    split_kernel<<<8192, 256>>>((const float4*)x,  (__nv_bfloat16*)xh,  (__nv_bfloat16*)xl,  8192 * 1024 / 4);
    split_kernel<<<3072, 256>>>((const float4*)Wa, (__nv_bfloat16*)Wah, (__nv_bfloat16*)Wal, 1024 * 3072 / 4);
    split_kernel<<<1024, 256>>>((const float4*)Wp, (__nv_bfloat16*)Wph, (__nv_bfloat16*)Wpl, 1024 * 1024 / 4);

    gemm_kernel<<<dim3(3072 / 128, 8192 / 128), 256, 75776>>>(
        (const __nv_bfloat16*)xh, (const __nv_bfloat16*)xl,
        (const __nv_bfloat16*)Wah, (const __nv_bfloat16*)Wal,
        ba, nullptr, (__nv_bfloat16*)qh, (__nv_bfloat16*)ql,
        8192, 3072, 1024);

    attn_kernel<<<dim3(TT / 128, 64), 256, 73728>>>();

    gemm_kernel<<<dim3(1024 / 128, 8192 / 128), 256, 75776>>>(
        (const __nv_bfloat16*)yh, (const __nv_bfloat16*)yl,
        (const __nv_bfloat16*)Wph, (const __nv_bfloat16*)Wpl,
        bp, out, nullptr, nullptr,
        8192, 1024, 1024);
}